// round 17
// baseline (speedup 1.0000x reference)
#include <cuda_runtime.h>
#include <cuda_bf16.h>

typedef unsigned int u32; typedef unsigned short u16; typedef unsigned long long u64;

#define HWD    (96*96*96)
#define TILESB (HWD/128)     // 6912 (divisible by TPC -> same batch per block)
#define TILES  (2*TILESB)    // 13824
#define TPC    8
#define GRID_X (TILES/TPC)   // 1728

// smem byte offsets; ONE A tile (AE then AX, ping-pong), 128 rows x 128B swizzled
#define SM_W   0
#define SM_A   1024
#define SM_B1  17408         // 4KB
#define SM_B2  21504         // 8KB
#define SM_B3  29696         // 8KB
#define SM_TOT 37888

static __device__ __forceinline__ u32 su32(const void* p) {
    return (u32)__cvta_generic_to_shared((void*)p);
}
static __device__ __forceinline__ void ldm4(u32* r, u32 addr) {
    asm volatile("ldmatrix.sync.aligned.m8n8.x4.shared.b16 {%0,%1,%2,%3}, [%4];"
        : "=r"(r[0]), "=r"(r[1]), "=r"(r[2]), "=r"(r[3]) : "r"(addr) : "memory");
}
static __device__ __forceinline__ void mma16816(float* c, const u32* a, u64 b) {
    asm volatile("mma.sync.aligned.m16n8k16.row.col.f32.bf16.bf16.f32 "
        "{%0,%1,%2,%3}, {%4,%5,%6,%7}, {%8,%9}, {%0,%1,%2,%3};"
        : "+f"(c[0]), "+f"(c[1]), "+f"(c[2]), "+f"(c[3])
        : "r"(a[0]), "r"(a[1]), "r"(a[2]), "r"(a[3]),
          "r"((u32)b), "r"((u32)(b >> 32)));
}
// pair of (hi,lo) u64 B-fragments with one LDS.128
static __device__ __forceinline__ void lds2(const u64* p, u64& a, u64& b) {
    asm volatile("ld.shared.v2.b64 {%0, %1}, [%2];"
        : "=l"(a), "=l"(b) : "l"(__cvta_generic_to_shared((void*)p)));
}
// ---- rn split (weights, one-time) ----
static __device__ __forceinline__ u16 bhi(float v) {
    return __bfloat16_as_ushort(__float2bfloat16_rn(v));
}
static __device__ __forceinline__ u16 blo(float v) {
    float r = v - __bfloat162float(__float2bfloat16_rn(v));
    return __bfloat16_as_ushort(__float2bfloat16_rn(r));
}
static __device__ __forceinline__ u32 packhi(float a, float b) {
    return (u32)bhi(a) | ((u32)bhi(b) << 16);
}
static __device__ __forceinline__ u32 packlo(float a, float b) {
    return (u32)blo(a) | ((u32)blo(b) << 16);
}
static __device__ __forceinline__ u64 bfrag(float w0, float w1, float w2, float w3, int take_hi) {
    u32 r0, r1;
    if (take_hi) { r0 = packhi(w0, w1); r1 = packhi(w2, w3); }
    else         { r0 = packlo(w0, w1); r1 = packlo(w2, w3); }
    return (u64)r0 | ((u64)r1 << 32);
}
// ---- truncation split (per-tile A packs): hi = bit-chop, lo = residual ----
static __device__ __forceinline__ u32 pack_thi(float a, float b) {
    u32 d;
    asm("prmt.b32 %0, %1, %2, 0x7632;" : "=r"(d)
        : "r"(__float_as_uint(a)), "r"(__float_as_uint(b)));
    return d;
}
static __device__ __forceinline__ u32 pack_tlo(float a, float b) {
    float ha = __uint_as_float(__float_as_uint(a) & 0xFFFF0000u);
    float hb = __uint_as_float(__float_as_uint(b) & 0xFFFF0000u);
    __nv_bfloat162 t = __floats2bfloat162_rn(a - ha, b - hb);
    return *(u32*)&t;
}
// store one swizzled 128B row from 32 packed u32
static __device__ __forceinline__ void strow(char* base, int row, const u32* q) {
    char* rp = base + row * 128; const int m = row & 7;
#pragma unroll
    for (int ch = 0; ch < 8; ++ch)
        *(uint4*)(rp + ((ch ^ m) * 16)) = make_uint4(q[ch*4], q[ch*4+1], q[ch*4+2], q[ch*4+3]);
}
static __device__ __forceinline__ u32 ldm_addr(u32 tileB, int row, int seg) {
    return tileB + (u32)row * 128 + (u32)((seg ^ (row & 7)) << 4);
}

__global__ void __launch_bounds__(128, 5)
fused_kernel(const float* __restrict__ x, const float* __restrict__ d_all,
             const float* __restrict__ W1, const float* __restrict__ W2,
             const float* __restrict__ G1, const float* __restrict__ G2,
             const float* __restrict__ G3, float* __restrict__ out)
{
    extern __shared__ char dsm[];
    const int tid = threadIdx.x, lane = tid & 31, wid = tid >> 5;
    float* sW = (float*)(dsm + SM_W);
    u64* sB1 = (u64*)(dsm + SM_B1);
    u64* sB2 = (u64*)(dsm + SM_B2);
    u64* sB3 = (u64*)(dsm + SM_B3);

    for (int i = tid; i < 32; i += 128) sW[i] = W1[i];
    for (int i = tid; i < 48; i += 128) sW[32+i] = W2[i];
    // B fragments: index ((nt*2+kc)*32+lane)*2 + hl  (hl: 0=hi, 1=lo)
    {
        const int n = lane >> 2;
        for (int f = wid; f < 16; f += 4) {          // GEMM1: G1 [32x27]
            int nt = f >> 2, kc = (f >> 1) & 1, hl = f & 1;
            int nn = nt*8 + n, cb = kc*16 + (lane&3)*2;
            float w0 = (cb   < 27) ? G1[nn*27+cb]   : 0.f;
            float w1 = (cb+1 < 27) ? G1[nn*27+cb+1] : 0.f;
            float w2 = (cb+8 < 27) ? G1[nn*27+cb+8] : 0.f;
            float w3 = (cb+9 < 27) ? G1[nn*27+cb+9] : 0.f;
            sB1[((nt*2+kc)*32+lane)*2 + hl] = bfrag(w0, w1, w2, w3, hl == 0);
        }
        for (int f = wid; f < 32; f += 4) {          // GEMM2: G2 [64x32]
            int nt = f >> 2, kc = (f >> 1) & 1, hl = f & 1;
            int nn = nt*8 + n, cb = kc*16 + (lane&3)*2;
            sB2[((nt*2+kc)*32+lane)*2 + hl] =
                bfrag(G2[nn*32+cb], G2[nn*32+cb+1],
                      G2[nn*32+cb+8], G2[nn*32+cb+9], hl == 0);
        }
        for (int f = wid; f < 32; f += 4) {          // GEMM3: G3 [32x64], B[k][n]=G3[k][n]
            int nt = f >> 2, kc = (f >> 1) & 1, hl = f & 1;
            int nn = nt*8 + n, cb = kc*16 + (lane&3)*2;
            sB3[((nt*2+kc)*32+lane)*2 + hl] =
                bfrag(G3[cb*64+nn], G3[(cb+1)*64+nn],
                      G3[(cb+8)*64+nn], G3[(cb+9)*64+nn], hl == 0);
        }
    }
    __syncthreads();

    const u32 aB = su32(dsm + SM_A);
    const int rbase = wid * 32;

    // all 8 tiles of this block share one batch index
    const int tile0 = blockIdx.x * TPC;
    const int b = (tile0 >= TILESB) ? 1 : 0;
    const float* xbase = x + (long long)b*32*HWD - (long long)b*HWD;
    const float* dbase = d_all + (long long)b*6*HWD - (long long)b*HWD;

    // preload dv for iteration 0
    float dv[6];
    {
        const float* db = dbase + (long long)tile0*128 + tid;
#pragma unroll
        for (int a = 0; a < 6; ++a) dv[a] = db[(long long)a*HWD];
    }

    for (int it = 0; it < TPC; ++it) {
        const int tile = tile0 + it;
        const long long gvox = (long long)tile * 128 + tid;

        // ---- issue x loads up front; encode+AE pack covers latency ----
        const float* xb = xbase + gvox;
        float v[32];
#pragma unroll
        for (int c = 0; c < 32; ++c) v[c] = xb[(long long)c*HWD];

        // ---- encode -> e[3][3], pij[9]; kron folded into the AE pack ----
        {
            float e[3][3];
#pragma unroll
            for (int a = 0; a < 3; ++a) {
                float a0 = 0.f, a1 = 0.f, a2 = 0.f;
#pragma unroll
                for (int j = 0; j < 16; ++j) {
                    float t = fmaxf(fmaf(sW[2*j], dv[2*a], sW[2*j+1]*dv[2*a+1]), 0.f);
                    a0 = fmaf(sW[32+j], t, a0); a1 = fmaf(sW[48+j], t, a1); a2 = fmaf(sW[64+j], t, a2);
                }
                e[a][0] = a0; e[a][1] = a1; e[a][2] = a2;
            }
            float pij[9];
#pragma unroll
            for (int i = 0; i < 3; ++i)
#pragma unroll
                for (int j = 0; j < 3; ++j) pij[i*3+j] = e[0][i] * e[1][j];
            u32 q[32];
#pragma unroll
            for (int i = 0; i < 16; ++i) {
                const int s0 = 2*i, s1 = 2*i + 1;
                float f0 = (s0 < 27) ? pij[s0/3] * e[2][s0%3] : 0.f;
                float f1 = (s1 < 27) ? pij[s1/3] * e[2][s1%3] : 0.f;
                q[i]      = pack_thi(f0, f1);
                q[16 + i] = pack_tlo(f0, f1);
            }
            strow(dsm + SM_A, tid, q);   // AE into shared tile
        }
        __syncwarp();
        u32 ae[2][4][4];
#pragma unroll
        for (int mt = 0; mt < 2; ++mt)
#pragma unroll
            for (int kt = 0; kt < 4; ++kt) {
                int row = rbase + mt*16 + (lane & 15), seg = kt*2 + (lane >> 4);
                ldm4(ae[mt][kt], ldm_addr(aB, row, seg));
            }
        __syncwarp();   // all ae reads done before AX overwrites the tile

        // ---- pack A_x into the SAME tile (v dies here) ----
        {
            u32 q[32];
#pragma unroll
            for (int i = 0; i < 16; ++i) {
                q[i]      = pack_thi(v[2*i], v[2*i+1]);
                q[16 + i] = pack_tlo(v[2*i], v[2*i+1]);
            }
            strow(dsm + SM_A, tid, q);
        }
        __syncwarp();

        // ---- GEMM1: H = E*G1^T (3-term), relu+pack C-frags -> A-frags ----
        u32 ah[2][4][4];
        {
            float hc[4][2][4];
#pragma unroll
            for (int nt = 0; nt < 4; ++nt) {
#pragma unroll
                for (int mt = 0; mt < 2; ++mt)
#pragma unroll
                    for (int r = 0; r < 4; ++r) hc[nt][mt][r] = 0.f;
#pragma unroll
                for (int kc = 0; kc < 2; ++kc) {
                    u64 bh, bl;
                    lds2(&sB1[((nt*2+kc)*32+lane)*2], bh, bl);
                    mma16816(hc[nt][0], ae[0][kc],   bh);
                    mma16816(hc[nt][1], ae[1][kc],   bh);
                    mma16816(hc[nt][0], ae[0][kc],   bl);
                    mma16816(hc[nt][1], ae[1][kc],   bl);
                    mma16816(hc[nt][0], ae[0][kc+2], bh);
                    mma16816(hc[nt][1], ae[1][kc+2], bh);
                }
            }
#pragma unroll
            for (int nt = 0; nt < 4; ++nt)
#pragma unroll
                for (int mt = 0; mt < 2; ++mt)
#pragma unroll
                    for (int r = 0; r < 4; ++r) hc[nt][mt][r] = fmaxf(hc[nt][mt][r], 0.f);
#pragma unroll
            for (int mt = 0; mt < 2; ++mt)
#pragma unroll
                for (int kc = 0; kc < 2; ++kc) {
                    ah[mt][kc][0]   = pack_thi(hc[2*kc][mt][0],   hc[2*kc][mt][1]);
                    ah[mt][kc][1]   = pack_thi(hc[2*kc][mt][2],   hc[2*kc][mt][3]);
                    ah[mt][kc][2]   = pack_thi(hc[2*kc+1][mt][0], hc[2*kc+1][mt][1]);
                    ah[mt][kc][3]   = pack_thi(hc[2*kc+1][mt][2], hc[2*kc+1][mt][3]);
                    ah[mt][kc+2][0] = pack_tlo(hc[2*kc][mt][0],   hc[2*kc][mt][1]);
                    ah[mt][kc+2][1] = pack_tlo(hc[2*kc][mt][2],   hc[2*kc][mt][3]);
                    ah[mt][kc+2][2] = pack_tlo(hc[2*kc+1][mt][0], hc[2*kc+1][mt][1]);
                    ah[mt][kc+2][3] = pack_tlo(hc[2*kc+1][mt][2], hc[2*kc+1][mt][3]);
                }
        }

        // ---- prefetch next iteration's dv ----
        if (it + 1 < TPC) {
            const float* dbn = dbase + (long long)(tile + 1)*128 + tid;
#pragma unroll
            for (int a = 0; a < 6; ++a) dv[a] = dbn[(long long)a*HWD];
        }

        // ---- load ax fragments (AX already in the tile) ----
        u32 ax[2][4][4];
#pragma unroll
        for (int mt = 0; mt < 2; ++mt)
#pragma unroll
            for (int kt = 0; kt < 4; ++kt) {
                int row = rbase + mt*16 + (lane & 15), seg = kt*2 + (lane >> 4);
                ldm4(ax[mt][kt], ldm_addr(aB, row, seg));
            }

        // ---- GEMM2 (S=H*G2^T) + GEMM3 (Y=X*G3), 3-term, + epilogue ----
        {
            float racc[2][2] = {{0.f, 0.f}, {0.f, 0.f}};
#pragma unroll
            for (int nt = 0; nt < 8; ++nt) {
                float sc[2][4], yc[2][4];
#pragma unroll
                for (int mt = 0; mt < 2; ++mt)
#pragma unroll
                    for (int r = 0; r < 4; ++r) { sc[mt][r] = 0.f; yc[mt][r] = 0.f; }
#pragma unroll
                for (int kc = 0; kc < 2; ++kc) {
                    u64 b2h, b2l, b3h, b3l;
                    lds2(&sB2[((nt*2+kc)*32+lane)*2], b2h, b2l);
                    lds2(&sB3[((nt*2+kc)*32+lane)*2], b3h, b3l);
                    mma16816(sc[0], ah[0][kc],   b2h);
                    mma16816(sc[1], ah[1][kc],   b2h);
                    mma16816(yc[0], ax[0][kc],   b3h);
                    mma16816(yc[1], ax[1][kc],   b3h);
                    mma16816(sc[0], ah[0][kc],   b2l);
                    mma16816(sc[1], ah[1][kc],   b2l);
                    mma16816(yc[0], ax[0][kc],   b3l);
                    mma16816(yc[1], ax[1][kc],   b3l);
                    mma16816(sc[0], ah[0][kc+2], b2h);
                    mma16816(sc[1], ah[1][kc+2], b2h);
                    mma16816(yc[0], ax[0][kc+2], b3h);
                    mma16816(yc[1], ax[1][kc+2], b3h);
                }
#pragma unroll
                for (int mt = 0; mt < 2; ++mt) {
                    racc[mt][0] += fmaxf(sc[mt][0], 0.f)*yc[mt][0] + fmaxf(sc[mt][1], 0.f)*yc[mt][1];
                    racc[mt][1] += fmaxf(sc[mt][2], 0.f)*yc[mt][2] + fmaxf(sc[mt][3], 0.f)*yc[mt][3];
                }
            }
            const long long gb = (long long)tile * 128 + rbase;
#pragma unroll
            for (int mt = 0; mt < 2; ++mt)
#pragma unroll
                for (int r = 0; r < 2; ++r) {
                    float s = racc[mt][r];
                    s += __shfl_xor_sync(0xFFFFFFFFu, s, 1);
                    s += __shfl_xor_sync(0xFFFFFFFFu, s, 2);
                    if ((lane & 3) == 0)
                        out[gb + mt*16 + (lane >> 2) + r*8] = s;
                }
        }
        __syncwarp();   // ax reads done before next iteration's AE stores
    }
}

extern "C" void kernel_launch(void* const* d_in, const int* in_sizes, int n_in,
                              void* d_out, int out_size)
{
    const float* x    = (const float*)d_in[0];
    const float* dall = (const float*)d_in[1];
    const float* W1   = (const float*)d_in[2];
    const float* W2   = (const float*)d_in[3];
    const float* G1   = (const float*)d_in[4];
    const float* G2   = (const float*)d_in[5];
    const float* G3   = (const float*)d_in[6];
    float* out = (float*)d_out;

    cudaFuncSetAttribute(fused_kernel, cudaFuncAttributeMaxDynamicSharedMemorySize, SM_TOT);
    fused_kernel<<<GRID_X, 128, SM_TOT>>>(x, dall, W1, W2, G1, G2, G3, out);
}